// round 1
// baseline (speedup 1.0000x reference)
#include <cuda_runtime.h>

#define IN   128
#define HID  128
#define OUTF 64
#define NMAX 50000

// Scratch (device globals; no allocation allowed)
__device__ float g_y1[NMAX * HID];    // (x@W1)*dinv[row]
__device__ float g_agg1[NMAX * HID];  // aggregated layer1 (pre dinv[dst]/bias/relu)
__device__ float g_y2[NMAX * OUTF];   // (h@W2)*dinv[row]
__device__ float g_agg2[NMAX * OUTF]; // aggregated layer2; becomes z in-place
__device__ float g_dinv[NMAX];
__device__ int   g_deg[NMAX];

// ---------------- degree / normalization ----------------
__global__ void k_deg_init(int n) {
    int i = blockIdx.x * blockDim.x + threadIdx.x;
    if (i < n) g_deg[i] = 1;  // self loop
}

__global__ void k_deg_count(const int* __restrict__ ei, int E) {
    int e = blockIdx.x * blockDim.x + threadIdx.x;
    if (e < E) atomicAdd(&g_deg[ei[E + e]], 1);  // dst row
}

__global__ void k_dinv(int n) {
    int i = blockIdx.x * blockDim.x + threadIdx.x;
    if (i < n) g_dinv[i] = rsqrtf((float)g_deg[i]);
}

// ---------------- GEMM1: y1 = (x @ W1) * dinv[row]; agg1 = y1 ----------------
// Block: 256 threads, 32 rows. Warp handles 4 rows x 128 cols (lane -> 4 cols).
__global__ void __launch_bounds__(256) k_gemm1(const float* __restrict__ x,
                                               const float* __restrict__ W1,
                                               int n) {
    __shared__ float xs[32 * 128];
    int row0 = blockIdx.x * 32;

    // load x tile (float4)
    for (int i = threadIdx.x; i < 32 * 32; i += 256) {
        int r = i >> 5;
        float4 v = make_float4(0.f, 0.f, 0.f, 0.f);
        if (row0 + r < n) v = ((const float4*)x)[(size_t)(row0 + r) * 32 + (i & 31)];
        ((float4*)xs)[i] = v;
    }
    __syncthreads();

    int warp = threadIdx.x >> 5;
    int lane = threadIdx.x & 31;
    int r0 = warp * 4;
    int c0 = lane * 4;

    float acc[4][4];
#pragma unroll
    for (int r = 0; r < 4; r++)
#pragma unroll
        for (int c = 0; c < 4; c++) acc[r][c] = 0.f;

#pragma unroll 4
    for (int k = 0; k < 128; k++) {
        float4 w = __ldg((const float4*)(W1 + k * 128 + c0));  // L1-resident
        float xv0 = xs[(r0 + 0) * 128 + k];
        float xv1 = xs[(r0 + 1) * 128 + k];
        float xv2 = xs[(r0 + 2) * 128 + k];
        float xv3 = xs[(r0 + 3) * 128 + k];
        acc[0][0] += xv0 * w.x; acc[0][1] += xv0 * w.y; acc[0][2] += xv0 * w.z; acc[0][3] += xv0 * w.w;
        acc[1][0] += xv1 * w.x; acc[1][1] += xv1 * w.y; acc[1][2] += xv1 * w.z; acc[1][3] += xv1 * w.w;
        acc[2][0] += xv2 * w.x; acc[2][1] += xv2 * w.y; acc[2][2] += xv2 * w.z; acc[2][3] += xv2 * w.w;
        acc[3][0] += xv3 * w.x; acc[3][1] += xv3 * w.y; acc[3][2] += xv3 * w.z; acc[3][3] += xv3 * w.w;
    }

#pragma unroll
    for (int r = 0; r < 4; r++) {
        int row = row0 + r0 + r;
        if (row < n) {
            float d = g_dinv[row];
            float4 v = make_float4(acc[r][0] * d, acc[r][1] * d, acc[r][2] * d, acc[r][3] * d);
            ((float4*)g_y1)[(size_t)row * 32 + lane]   = v;
            ((float4*)g_agg1)[(size_t)row * 32 + lane] = v;  // self-loop init
        }
    }
}

// ---------------- edge scatter layer1: agg1[dst] += y1[src] (128 floats) ----------------
__global__ void __launch_bounds__(256) k_scatter1(const int* __restrict__ ei, int E) {
    int w = (int)((blockIdx.x * 256u + threadIdx.x) >> 5);
    int lane = threadIdx.x & 31;
    if (w >= E) return;
    int src = ei[w];
    int dst = ei[E + w];
    float4 v = ((const float4*)g_y1)[(size_t)src * 32 + lane];
    float* p = g_agg1 + (size_t)dst * 128 + lane * 4;
    asm volatile("red.global.add.v4.f32 [%0], {%1,%2,%3,%4};"
                 :: "l"(p), "f"(v.x), "f"(v.y), "f"(v.z), "f"(v.w) : "memory");
}

// ---------------- GEMM2: h = relu(agg1*dinv + b1) on the fly; y2=(h@W2)*dinv; agg2=y2 ----
// Block: 256 threads, 64 rows. Warp handles 8 rows x 64 cols (lane -> 2 cols).
__global__ void __launch_bounds__(256) k_gemm2(const float* __restrict__ W2,
                                               const float* __restrict__ b1,
                                               int n) {
    __shared__ float hs[64 * 128];
    int row0 = blockIdx.x * 64;

    for (int i = threadIdx.x; i < 64 * 32; i += 256) {
        int r = i >> 5;
        int c4 = i & 31;
        float4 v = make_float4(0.f, 0.f, 0.f, 0.f);
        int row = row0 + r;
        if (row < n) {
            float4 a  = ((const float4*)g_agg1)[(size_t)row * 32 + c4];
            float4 bb = ((const float4*)b1)[c4];
            float d = g_dinv[row];
            v.x = fmaxf(a.x * d + bb.x, 0.f);
            v.y = fmaxf(a.y * d + bb.y, 0.f);
            v.z = fmaxf(a.z * d + bb.z, 0.f);
            v.w = fmaxf(a.w * d + bb.w, 0.f);
        }
        ((float4*)hs)[i] = v;
    }
    __syncthreads();

    int warp = threadIdx.x >> 5;
    int lane = threadIdx.x & 31;
    int r0 = warp * 8;
    int c0 = lane * 2;

    float acc[8][2];
#pragma unroll
    for (int r = 0; r < 8; r++) { acc[r][0] = 0.f; acc[r][1] = 0.f; }

#pragma unroll 4
    for (int k = 0; k < 128; k++) {
        float2 w = __ldg((const float2*)(W2 + k * 64 + c0));
#pragma unroll
        for (int r = 0; r < 8; r++) {
            float xv = hs[(r0 + r) * 128 + k];
            acc[r][0] += xv * w.x;
            acc[r][1] += xv * w.y;
        }
    }

#pragma unroll
    for (int r = 0; r < 8; r++) {
        int row = row0 + r0 + r;
        if (row < n) {
            float d = g_dinv[row];
            float2 v = make_float2(acc[r][0] * d, acc[r][1] * d);
            ((float2*)g_y2)[(size_t)row * 32 + lane]   = v;
            ((float2*)g_agg2)[(size_t)row * 32 + lane] = v;  // self-loop init
        }
    }
}

// ---------------- edge scatter layer2: agg2[dst] += y2[src] (64 floats) ----------------
__global__ void __launch_bounds__(256) k_scatter2(const int* __restrict__ ei, int E) {
    int w = (int)((blockIdx.x * 256u + threadIdx.x) >> 5);
    int lane = threadIdx.x & 31;
    if (w >= E) return;
    int src = ei[w];
    int dst = ei[E + w];
    float2 v = ((const float2*)g_y2)[(size_t)src * 32 + lane];
    float* p = g_agg2 + (size_t)dst * 64 + lane * 2;
    asm volatile("red.global.add.v2.f32 [%0], {%1,%2};"
                 :: "l"(p), "f"(v.x), "f"(v.y) : "memory");
}

// ---------------- z = agg2*dinv + b2 (in place) ----------------
__global__ void k_z(const float* __restrict__ b2, int n) {
    int i = blockIdx.x * blockDim.x + threadIdx.x;  // float4 index
    if (i >= n * 16) return;
    int row = i >> 4;
    int c4 = i & 15;
    float d = g_dinv[row];
    float4 a  = ((float4*)g_agg2)[i];
    float4 bb = ((const float4*)b2)[c4];
    a.x = a.x * d + bb.x;
    a.y = a.y * d + bb.y;
    a.z = a.z * d + bb.z;
    a.w = a.w * d + bb.w;
    ((float4*)g_agg2)[i] = a;
}

// ---------------- decode: logits[e] = dot(z[a], z[b]) over 64 dims ----------------
__global__ void __launch_bounds__(256) k_decode(const int* __restrict__ eli, int EL,
                                                float* __restrict__ out) {
    int w = (int)((blockIdx.x * 256u + threadIdx.x) >> 5);
    int lane = threadIdx.x & 31;
    if (w >= EL) return;
    int a = eli[w];
    int b = eli[EL + w];
    float2 za = ((const float2*)g_agg2)[(size_t)a * 32 + lane];
    float2 zb = ((const float2*)g_agg2)[(size_t)b * 32 + lane];
    float s = za.x * zb.x + za.y * zb.y;
#pragma unroll
    for (int o = 16; o; o >>= 1) s += __shfl_xor_sync(0xffffffffu, s, o);
    if (lane == 0) out[w] = s;
}

extern "C" void kernel_launch(void* const* d_in, const int* in_sizes, int n_in,
                              void* d_out, int out_size) {
    const float* x   = (const float*)d_in[0];
    const int*   ei  = (const int*)d_in[1];
    const int*   eli = (const int*)d_in[2];
    const float* W1  = (const float*)d_in[3];
    const float* b1  = (const float*)d_in[4];
    const float* W2  = (const float*)d_in[5];
    const float* b2  = (const float*)d_in[6];
    float* out = (float*)d_out;

    int N  = in_sizes[0] / IN;
    int E  = in_sizes[1] / 2;
    int EL = in_sizes[2] / 2;

    // normalization
    k_deg_init<<<(N + 255) / 256, 256>>>(N);
    k_deg_count<<<(E + 255) / 256, 256>>>(ei, E);
    k_dinv<<<(N + 255) / 256, 256>>>(N);

    // layer 1
    k_gemm1<<<(N + 31) / 32, 256>>>(x, W1, N);
    k_scatter1<<<(E * 32 + 255) / 256, 256>>>(ei, E);

    // layer 2 (h computed on the fly inside gemm2)
    k_gemm2<<<(N + 63) / 64, 256>>>(W2, b1, N);
    k_scatter2<<<(E * 32 + 255) / 256, 256>>>(ei, E);

    // z and decode
    k_z<<<(N * 16 + 255) / 256, 256>>>(b2, N);
    k_decode<<<(EL * 32 + 255) / 256, 256>>>(eli, EL, out);
}

// round 2
// speedup vs baseline: 1.7385x; 1.7385x over previous
#include <cuda_runtime.h>

#define IN   128
#define HID  128
#define OUTF 64
#define NMAX 50000
#define EMAX 1600000

// Scratch (device globals; no allocation allowed)
__device__ __align__(128) float g_y1[NMAX * HID];   // (x@W1)*dinv[row]
__device__ __align__(128) float g_h [NMAX * HID];   // relu-activated hidden
__device__ __align__(128) float g_y2[NMAX * OUTF];  // (h@W2)*dinv[row]
__device__ __align__(128) float g_z [NMAX * OUTF];  // final embeddings
__device__ float g_dinv[NMAX];
__device__ int   g_cnt[NMAX];
__device__ int   g_cur[NMAX];
__device__ int   g_off[NMAX + 1];
__device__ int   g_csr_src[EMAX];

// ---------------- CSR build ----------------
__global__ void k_zero_cnt(int n) {
    int i = blockIdx.x * blockDim.x + threadIdx.x;
    if (i < n) g_cnt[i] = 0;
}

__global__ void k_count(const int* __restrict__ ei, int E) {
    int e = blockIdx.x * blockDim.x + threadIdx.x;
    if (e < E) atomicAdd(&g_cnt[ei[E + e]], 1);  // dst
}

// single-block exclusive scan over g_cnt -> g_off; also dinv and cur=0
__global__ void __launch_bounds__(1024) k_scan(int n) {
    __shared__ int wsum[32];
    __shared__ int s_carry;
    int tid = threadIdx.x, lane = tid & 31, warp = tid >> 5;
    if (tid == 0) s_carry = 0;
    __syncthreads();
    for (int base = 0; base < n; base += 1024) {
        int i = base + tid;
        int v = (i < n) ? g_cnt[i] : 0;
        int x = v;
#pragma unroll
        for (int o = 1; o < 32; o <<= 1) {
            int t = __shfl_up_sync(0xffffffffu, x, o);
            if (lane >= o) x += t;
        }
        if (lane == 31) wsum[warp] = x;
        __syncthreads();
        if (warp == 0) {
            int y = wsum[lane];
#pragma unroll
            for (int o = 1; o < 32; o <<= 1) {
                int t = __shfl_up_sync(0xffffffffu, y, o);
                if (lane >= o) y += t;
            }
            wsum[lane] = y;
        }
        __syncthreads();
        int warpoff = (warp > 0) ? wsum[warp - 1] : 0;
        int incl = x + warpoff + s_carry;
        if (i < n) {
            g_off[i] = incl - v;
            g_dinv[i] = rsqrtf((float)(v + 1));  // +1 self loop
            g_cur[i] = 0;
        }
        __syncthreads();
        if (tid == 1023) s_carry = incl;
        __syncthreads();
    }
    if (threadIdx.x == 0) g_off[n] = s_carry;
}

__global__ void k_fill(const int* __restrict__ ei, int E) {
    int e = blockIdx.x * blockDim.x + threadIdx.x;
    if (e < E) {
        int s = ei[e];
        int d = ei[E + e];
        int pos = g_off[d] + atomicAdd(&g_cur[d], 1);
        g_csr_src[pos] = s;
    }
}

// ---------------- GEMM1: y1 = (x @ W1) * dinv[row] ----------------
// Block 256 = 8 warps; 64-row tile; warp = 8 rows x 128 cols (lane -> 4 cols)
__global__ void __launch_bounds__(256) k_gemm1(const float* __restrict__ x,
                                               const float* __restrict__ W1,
                                               int n) {
    __shared__ float xs[64 * 128];
    int row0 = blockIdx.x * 64;

    for (int i = threadIdx.x; i < 64 * 32; i += 256) {
        int r = i >> 5;
        float4 v = make_float4(0.f, 0.f, 0.f, 0.f);
        if (row0 + r < n) v = ((const float4*)x)[(size_t)(row0 + r) * 32 + (i & 31)];
        ((float4*)xs)[i] = v;
    }
    __syncthreads();

    int warp = threadIdx.x >> 5;
    int lane = threadIdx.x & 31;
    int r0 = warp * 8;
    int c0 = lane * 4;

    float acc[8][4];
#pragma unroll
    for (int r = 0; r < 8; r++)
#pragma unroll
        for (int c = 0; c < 4; c++) acc[r][c] = 0.f;

#pragma unroll 4
    for (int k = 0; k < 128; k++) {
        float4 w = __ldg((const float4*)(W1 + k * 128 + c0));
#pragma unroll
        for (int r = 0; r < 8; r++) {
            float xv = xs[(r0 + r) * 128 + k];
            acc[r][0] += xv * w.x;
            acc[r][1] += xv * w.y;
            acc[r][2] += xv * w.z;
            acc[r][3] += xv * w.w;
        }
    }

#pragma unroll
    for (int r = 0; r < 8; r++) {
        int row = row0 + r0 + r;
        if (row < n) {
            float d = g_dinv[row];
            float4 v = make_float4(acc[r][0] * d, acc[r][1] * d, acc[r][2] * d, acc[r][3] * d);
            ((float4*)g_y1)[(size_t)row * 32 + lane] = v;
        }
    }
}

// ---------------- agg1: h = relu((y1[i] + sum y1[src]) * dinv[i] + b1) ----------------
__global__ void __launch_bounds__(256) k_agg1(const float* __restrict__ b1, int n) {
    int node = (int)((blockIdx.x * 256u + threadIdx.x) >> 5);
    int lane = threadIdx.x & 31;
    if (node >= n) return;
    int beg = g_off[node];
    int end = g_off[node + 1];

    float4 acc = ((const float4*)g_y1)[(size_t)node * 32 + lane];  // self
    int j = beg;
    for (; j + 1 < end; j += 2) {
        int s0 = __ldg(&g_csr_src[j]);
        int s1 = __ldg(&g_csr_src[j + 1]);
        float4 v0 = ((const float4*)g_y1)[(size_t)s0 * 32 + lane];
        float4 v1 = ((const float4*)g_y1)[(size_t)s1 * 32 + lane];
        acc.x += v0.x; acc.y += v0.y; acc.z += v0.z; acc.w += v0.w;
        acc.x += v1.x; acc.y += v1.y; acc.z += v1.z; acc.w += v1.w;
    }
    if (j < end) {
        int s0 = __ldg(&g_csr_src[j]);
        float4 v0 = ((const float4*)g_y1)[(size_t)s0 * 32 + lane];
        acc.x += v0.x; acc.y += v0.y; acc.z += v0.z; acc.w += v0.w;
    }

    float d = g_dinv[node];
    float4 bb = ((const float4*)b1)[lane];
    float4 h;
    h.x = fmaxf(acc.x * d + bb.x, 0.f);
    h.y = fmaxf(acc.y * d + bb.y, 0.f);
    h.z = fmaxf(acc.z * d + bb.z, 0.f);
    h.w = fmaxf(acc.w * d + bb.w, 0.f);
    ((float4*)g_h)[(size_t)node * 32 + lane] = h;
}

// ---------------- GEMM2: y2 = (h @ W2) * dinv[row] ----------------
// Block 256 = 8 warps; 64-row tile; warp = 8 rows x 64 cols (lane -> 2 cols)
__global__ void __launch_bounds__(256) k_gemm2(const float* __restrict__ W2, int n) {
    __shared__ float hs[64 * 128];
    int row0 = blockIdx.x * 64;

    for (int i = threadIdx.x; i < 64 * 32; i += 256) {
        int r = i >> 5;
        float4 v = make_float4(0.f, 0.f, 0.f, 0.f);
        if (row0 + r < n) v = ((const float4*)g_h)[(size_t)(row0 + r) * 32 + (i & 31)];
        ((float4*)hs)[i] = v;
    }
    __syncthreads();

    int warp = threadIdx.x >> 5;
    int lane = threadIdx.x & 31;
    int r0 = warp * 8;
    int c0 = lane * 2;

    float acc[8][2];
#pragma unroll
    for (int r = 0; r < 8; r++) { acc[r][0] = 0.f; acc[r][1] = 0.f; }

#pragma unroll 4
    for (int k = 0; k < 128; k++) {
        float2 w = __ldg((const float2*)(W2 + k * 64 + c0));
#pragma unroll
        for (int r = 0; r < 8; r++) {
            float xv = hs[(r0 + r) * 128 + k];
            acc[r][0] += xv * w.x;
            acc[r][1] += xv * w.y;
        }
    }

#pragma unroll
    for (int r = 0; r < 8; r++) {
        int row = row0 + r0 + r;
        if (row < n) {
            float d = g_dinv[row];
            float2 v = make_float2(acc[r][0] * d, acc[r][1] * d);
            ((float2*)g_y2)[(size_t)row * 32 + lane] = v;
        }
    }
}

// ---------------- agg2: z = (y2[i] + sum y2[src]) * dinv[i] + b2 ----------------
__global__ void __launch_bounds__(256) k_agg2(const float* __restrict__ b2, int n) {
    int node = (int)((blockIdx.x * 256u + threadIdx.x) >> 5);
    int lane = threadIdx.x & 31;
    if (node >= n) return;
    int beg = g_off[node];
    int end = g_off[node + 1];

    float2 acc = ((const float2*)g_y2)[(size_t)node * 32 + lane];  // self
    int j = beg;
    for (; j + 1 < end; j += 2) {
        int s0 = __ldg(&g_csr_src[j]);
        int s1 = __ldg(&g_csr_src[j + 1]);
        float2 v0 = ((const float2*)g_y2)[(size_t)s0 * 32 + lane];
        float2 v1 = ((const float2*)g_y2)[(size_t)s1 * 32 + lane];
        acc.x += v0.x; acc.y += v0.y;
        acc.x += v1.x; acc.y += v1.y;
    }
    if (j < end) {
        int s0 = __ldg(&g_csr_src[j]);
        float2 v0 = ((const float2*)g_y2)[(size_t)s0 * 32 + lane];
        acc.x += v0.x; acc.y += v0.y;
    }

    float d = g_dinv[node];
    float2 bb = ((const float2*)b2)[lane];
    float2 z = make_float2(acc.x * d + bb.x, acc.y * d + bb.y);
    ((float2*)g_z)[(size_t)node * 32 + lane] = z;
}

// ---------------- decode: logits[e] = dot(z[a], z[b]) over 64 dims ----------------
__global__ void __launch_bounds__(256) k_decode(const int* __restrict__ eli, int EL,
                                                float* __restrict__ out) {
    int w = (int)((blockIdx.x * 256u + threadIdx.x) >> 5);
    int lane = threadIdx.x & 31;
    if (w >= EL) return;
    int a = eli[w];
    int b = eli[EL + w];
    float2 za = ((const float2*)g_z)[(size_t)a * 32 + lane];
    float2 zb = ((const float2*)g_z)[(size_t)b * 32 + lane];
    float s = za.x * zb.x + za.y * zb.y;
#pragma unroll
    for (int o = 16; o; o >>= 1) s += __shfl_xor_sync(0xffffffffu, s, o);
    if (lane == 0) out[w] = s;
}

extern "C" void kernel_launch(void* const* d_in, const int* in_sizes, int n_in,
                              void* d_out, int out_size) {
    const float* x   = (const float*)d_in[0];
    const int*   ei  = (const int*)d_in[1];
    const int*   eli = (const int*)d_in[2];
    const float* W1  = (const float*)d_in[3];
    const float* b1  = (const float*)d_in[4];
    const float* W2  = (const float*)d_in[5];
    const float* b2  = (const float*)d_in[6];
    float* out = (float*)d_out;

    int N  = in_sizes[0] / IN;
    int E  = in_sizes[1] / 2;
    int EL = in_sizes[2] / 2;

    // CSR build (by dst)
    k_zero_cnt<<<(N + 255) / 256, 256>>>(N);
    k_count<<<(E + 255) / 256, 256>>>(ei, E);
    k_scan<<<1, 1024>>>(N);
    k_fill<<<(E + 255) / 256, 256>>>(ei, E);

    // layer 1
    k_gemm1<<<(N + 63) / 64, 256>>>(x, W1, N);
    k_agg1<<<(N * 32 + 255) / 256, 256>>>(b1, N);

    // layer 2
    k_gemm2<<<(N + 63) / 64, 256>>>(W2, N);
    k_agg2<<<(N * 32 + 255) / 256, 256>>>(b2, N);

    // decode
    k_decode<<<(EL * 32 + 255) / 256, 256>>>(eli, EL, out);
}

// round 3
// speedup vs baseline: 1.7784x; 1.0229x over previous
#include <cuda_runtime.h>
#include <cuda_fp16.h>

#define IN   128
#define HID  128
#define OUTF 64
#define NMAX 50000
#define EMAX 1600000

// Scratch (device globals; no allocation allowed)
__device__ __align__(128) unsigned int g_y1h[NMAX * HID / 2];   // (x@W1)*dinv[row], half2 packed
__device__ __align__(128) float g_h [NMAX * HID];               // relu-activated hidden (fp32)
__device__ __align__(128) unsigned int g_y2h[NMAX * OUTF / 2];  // (h@W2)*dinv[row], half2 packed
__device__ __align__(128) float g_z [NMAX * OUTF];              // final embeddings
__device__ float g_dinv[NMAX];
__device__ int   g_cnt[NMAX];
__device__ int   g_cur[NMAX];
__device__ int   g_off[NMAX + 1];
__device__ int   g_csr_src[EMAX];

// ---------------- CSR build ----------------
__global__ void k_zero_cnt(int n) {
    int i = blockIdx.x * blockDim.x + threadIdx.x;
    if (i < n) g_cnt[i] = 0;
}

__global__ void __launch_bounds__(256) k_count(const int* __restrict__ ei, int E) {
    int stride = gridDim.x * blockDim.x;
    int e = blockIdx.x * blockDim.x + threadIdx.x;
#pragma unroll 4
    for (int k = 0; k < 4; k++) {
        int idx = e + k * stride;
        if (idx < E) atomicAdd(&g_cnt[ei[E + idx]], 1);  // dst
    }
}

// single-block exclusive scan over g_cnt -> g_off; also dinv and cur=0
__global__ void __launch_bounds__(1024) k_scan(int n) {
    __shared__ int wsum[32];
    __shared__ int s_carry;
    int tid = threadIdx.x, lane = tid & 31, warp = tid >> 5;
    if (tid == 0) s_carry = 0;
    __syncthreads();
    for (int base = 0; base < n; base += 1024) {
        int i = base + tid;
        int v = (i < n) ? g_cnt[i] : 0;
        int x = v;
#pragma unroll
        for (int o = 1; o < 32; o <<= 1) {
            int t = __shfl_up_sync(0xffffffffu, x, o);
            if (lane >= o) x += t;
        }
        if (lane == 31) wsum[warp] = x;
        __syncthreads();
        if (warp == 0) {
            int y = wsum[lane];
#pragma unroll
            for (int o = 1; o < 32; o <<= 1) {
                int t = __shfl_up_sync(0xffffffffu, y, o);
                if (lane >= o) y += t;
            }
            wsum[lane] = y;
        }
        __syncthreads();
        int warpoff = (warp > 0) ? wsum[warp - 1] : 0;
        int incl = x + warpoff + s_carry;
        if (i < n) {
            g_off[i] = incl - v;
            g_dinv[i] = rsqrtf((float)(v + 1));  // +1 self loop
            g_cur[i] = 0;
        }
        __syncthreads();
        if (tid == 1023) s_carry = incl;
        __syncthreads();
    }
    if (threadIdx.x == 0) g_off[n] = s_carry;
}

__global__ void __launch_bounds__(256) k_fill(const int* __restrict__ ei, int E) {
    int stride = gridDim.x * blockDim.x;
    int e = blockIdx.x * blockDim.x + threadIdx.x;
#pragma unroll 4
    for (int k = 0; k < 4; k++) {
        int idx = e + k * stride;
        if (idx < E) {
            int s = ei[idx];
            int d = ei[E + idx];
            int pos = g_off[d] + atomicAdd(&g_cur[d], 1);
            g_csr_src[pos] = s;
        }
    }
}

// ---------------- GEMM1: y1 = (x @ W1) * dinv[row], fp16 out ----------------
// Block 256 = 8 warps; 64-row tile; warp = 8 rows x 128 cols (lane -> 4 cols)
__global__ void __launch_bounds__(256) k_gemm1(const float* __restrict__ x,
                                               const float* __restrict__ W1,
                                               int n) {
    __shared__ float xs[64 * 128];
    int row0 = blockIdx.x * 64;

    for (int i = threadIdx.x; i < 64 * 32; i += 256) {
        int r = i >> 5;
        float4 v = make_float4(0.f, 0.f, 0.f, 0.f);
        if (row0 + r < n) v = ((const float4*)x)[(size_t)(row0 + r) * 32 + (i & 31)];
        ((float4*)xs)[i] = v;
    }
    __syncthreads();

    int warp = threadIdx.x >> 5;
    int lane = threadIdx.x & 31;
    int r0 = warp * 8;
    int c0 = lane * 4;

    float acc[8][4];
#pragma unroll
    for (int r = 0; r < 8; r++)
#pragma unroll
        for (int c = 0; c < 4; c++) acc[r][c] = 0.f;

#pragma unroll 4
    for (int k = 0; k < 128; k++) {
        float4 w = __ldg((const float4*)(W1 + k * 128 + c0));
#pragma unroll
        for (int r = 0; r < 8; r++) {
            float xv = xs[(r0 + r) * 128 + k];
            acc[r][0] += xv * w.x;
            acc[r][1] += xv * w.y;
            acc[r][2] += xv * w.z;
            acc[r][3] += xv * w.w;
        }
    }

#pragma unroll
    for (int r = 0; r < 8; r++) {
        int row = row0 + r0 + r;
        if (row < n) {
            float d = g_dinv[row];
            half2 h0 = __float22half2_rn(make_float2(acc[r][0] * d, acc[r][1] * d));
            half2 h1 = __float22half2_rn(make_float2(acc[r][2] * d, acc[r][3] * d));
            uint2 p;
            p.x = *(unsigned int*)&h0;
            p.y = *(unsigned int*)&h1;
            ((uint2*)g_y1h)[(size_t)row * 32 + lane] = p;
        }
    }
}

// ---------------- agg1: h = relu((y1[i] + sum y1[src]) * dinv[i] + b1) ----------------
__global__ void __launch_bounds__(256) k_agg1(const float* __restrict__ b1, int n) {
    int node = (int)((blockIdx.x * 256u + threadIdx.x) >> 5);
    int lane = threadIdx.x & 31;
    if (node >= n) return;
    int beg = g_off[node];
    int end = g_off[node + 1];

    const uint2* y = (const uint2*)g_y1h;
    uint2 ps = y[(size_t)node * 32 + lane];  // self
    float2 a0 = __half22float2(*(half2*)&ps.x);
    float2 a1 = __half22float2(*(half2*)&ps.y);
    float4 acc = make_float4(a0.x, a0.y, a1.x, a1.y);

    int j = beg;
    for (; j + 3 < end; j += 4) {
        int s0 = __ldg(&g_csr_src[j]);
        int s1 = __ldg(&g_csr_src[j + 1]);
        int s2 = __ldg(&g_csr_src[j + 2]);
        int s3 = __ldg(&g_csr_src[j + 3]);
        uint2 p0 = y[(size_t)s0 * 32 + lane];
        uint2 p1 = y[(size_t)s1 * 32 + lane];
        uint2 p2 = y[(size_t)s2 * 32 + lane];
        uint2 p3 = y[(size_t)s3 * 32 + lane];
        float2 u, v;
        u = __half22float2(*(half2*)&p0.x); v = __half22float2(*(half2*)&p0.y);
        acc.x += u.x; acc.y += u.y; acc.z += v.x; acc.w += v.y;
        u = __half22float2(*(half2*)&p1.x); v = __half22float2(*(half2*)&p1.y);
        acc.x += u.x; acc.y += u.y; acc.z += v.x; acc.w += v.y;
        u = __half22float2(*(half2*)&p2.x); v = __half22float2(*(half2*)&p2.y);
        acc.x += u.x; acc.y += u.y; acc.z += v.x; acc.w += v.y;
        u = __half22float2(*(half2*)&p3.x); v = __half22float2(*(half2*)&p3.y);
        acc.x += u.x; acc.y += u.y; acc.z += v.x; acc.w += v.y;
    }
    for (; j < end; j++) {
        int s0 = __ldg(&g_csr_src[j]);
        uint2 p0 = y[(size_t)s0 * 32 + lane];
        float2 u = __half22float2(*(half2*)&p0.x);
        float2 v = __half22float2(*(half2*)&p0.y);
        acc.x += u.x; acc.y += u.y; acc.z += v.x; acc.w += v.y;
    }

    float d = g_dinv[node];
    float4 bb = ((const float4*)b1)[lane];
    float4 h;
    h.x = fmaxf(acc.x * d + bb.x, 0.f);
    h.y = fmaxf(acc.y * d + bb.y, 0.f);
    h.z = fmaxf(acc.z * d + bb.z, 0.f);
    h.w = fmaxf(acc.w * d + bb.w, 0.f);
    ((float4*)g_h)[(size_t)node * 32 + lane] = h;
}

// ---------------- GEMM2: y2 = (h @ W2) * dinv[row], fp16 out ----------------
// Block 256 = 8 warps; 64-row tile; warp = 8 rows x 64 cols (lane -> 2 cols)
__global__ void __launch_bounds__(256) k_gemm2(const float* __restrict__ W2, int n) {
    __shared__ float hs[64 * 128];
    int row0 = blockIdx.x * 64;

    for (int i = threadIdx.x; i < 64 * 32; i += 256) {
        int r = i >> 5;
        float4 v = make_float4(0.f, 0.f, 0.f, 0.f);
        if (row0 + r < n) v = ((const float4*)g_h)[(size_t)(row0 + r) * 32 + (i & 31)];
        ((float4*)hs)[i] = v;
    }
    __syncthreads();

    int warp = threadIdx.x >> 5;
    int lane = threadIdx.x & 31;
    int r0 = warp * 8;
    int c0 = lane * 2;

    float acc[8][2];
#pragma unroll
    for (int r = 0; r < 8; r++) { acc[r][0] = 0.f; acc[r][1] = 0.f; }

#pragma unroll 4
    for (int k = 0; k < 128; k++) {
        float2 w = __ldg((const float2*)(W2 + k * 64 + c0));
#pragma unroll
        for (int r = 0; r < 8; r++) {
            float xv = hs[(r0 + r) * 128 + k];
            acc[r][0] += xv * w.x;
            acc[r][1] += xv * w.y;
        }
    }

#pragma unroll
    for (int r = 0; r < 8; r++) {
        int row = row0 + r0 + r;
        if (row < n) {
            float d = g_dinv[row];
            half2 hv = __float22half2_rn(make_float2(acc[r][0] * d, acc[r][1] * d));
            g_y2h[(size_t)row * 32 + lane] = *(unsigned int*)&hv;
        }
    }
}

// ---------------- agg2: z = (y2[i] + sum y2[src]) * dinv[i] + b2 ----------------
__global__ void __launch_bounds__(256) k_agg2(const float* __restrict__ b2, int n) {
    int node = (int)((blockIdx.x * 256u + threadIdx.x) >> 5);
    int lane = threadIdx.x & 31;
    if (node >= n) return;
    int beg = g_off[node];
    int end = g_off[node + 1];

    const unsigned int* y = g_y2h;
    unsigned int ps = y[(size_t)node * 32 + lane];  // self
    float2 acc = __half22float2(*(half2*)&ps);

    int j = beg;
    for (; j + 3 < end; j += 4) {
        int s0 = __ldg(&g_csr_src[j]);
        int s1 = __ldg(&g_csr_src[j + 1]);
        int s2 = __ldg(&g_csr_src[j + 2]);
        int s3 = __ldg(&g_csr_src[j + 3]);
        unsigned int p0 = y[(size_t)s0 * 32 + lane];
        unsigned int p1 = y[(size_t)s1 * 32 + lane];
        unsigned int p2 = y[(size_t)s2 * 32 + lane];
        unsigned int p3 = y[(size_t)s3 * 32 + lane];
        float2 u;
        u = __half22float2(*(half2*)&p0); acc.x += u.x; acc.y += u.y;
        u = __half22float2(*(half2*)&p1); acc.x += u.x; acc.y += u.y;
        u = __half22float2(*(half2*)&p2); acc.x += u.x; acc.y += u.y;
        u = __half22float2(*(half2*)&p3); acc.x += u.x; acc.y += u.y;
    }
    for (; j < end; j++) {
        int s0 = __ldg(&g_csr_src[j]);
        unsigned int p0 = y[(size_t)s0 * 32 + lane];
        float2 u = __half22float2(*(half2*)&p0);
        acc.x += u.x; acc.y += u.y;
    }

    float d = g_dinv[node];
    float2 bb = ((const float2*)b2)[lane];
    float2 z = make_float2(acc.x * d + bb.x, acc.y * d + bb.y);
    ((float2*)g_z)[(size_t)node * 32 + lane] = z;
}

// ---------------- decode: logits[e] = dot(z[a], z[b]) over 64 dims ----------------
__global__ void __launch_bounds__(256) k_decode(const int* __restrict__ eli, int EL,
                                                float* __restrict__ out) {
    int w = (int)((blockIdx.x * 256u + threadIdx.x) >> 5);
    int lane = threadIdx.x & 31;
    if (w >= EL) return;
    int a = eli[w];
    int b = eli[EL + w];
    float2 za = ((const float2*)g_z)[(size_t)a * 32 + lane];
    float2 zb = ((const float2*)g_z)[(size_t)b * 32 + lane];
    float s = za.x * zb.x + za.y * zb.y;
#pragma unroll
    for (int o = 16; o; o >>= 1) s += __shfl_xor_sync(0xffffffffu, s, o);
    if (lane == 0) out[w] = s;
}

extern "C" void kernel_launch(void* const* d_in, const int* in_sizes, int n_in,
                              void* d_out, int out_size) {
    const float* x   = (const float*)d_in[0];
    const int*   ei  = (const int*)d_in[1];
    const int*   eli = (const int*)d_in[2];
    const float* W1  = (const float*)d_in[3];
    const float* b1  = (const float*)d_in[4];
    const float* W2  = (const float*)d_in[5];
    const float* b2  = (const float*)d_in[6];
    float* out = (float*)d_out;

    int N  = in_sizes[0] / IN;
    int E  = in_sizes[1] / 2;
    int EL = in_sizes[2] / 2;

    int quarter = (E + 3) / 4;

    // CSR build (by dst)
    k_zero_cnt<<<(N + 255) / 256, 256>>>(N);
    k_count<<<(quarter + 255) / 256, 256>>>(ei, E);
    k_scan<<<1, 1024>>>(N);
    k_fill<<<(quarter + 255) / 256, 256>>>(ei, E);

    // layer 1
    k_gemm1<<<(N + 63) / 64, 256>>>(x, W1, N);
    k_agg1<<<(N * 32 + 255) / 256, 256>>>(b1, N);

    // layer 2
    k_gemm2<<<(N + 63) / 64, 256>>>(W2, N);
    k_agg2<<<(N * 32 + 255) / 256, 256>>>(b2, N);

    // decode
    k_decode<<<(EL * 32 + 255) / 256, 256>>>(eli, EL, out);
}

// round 4
// speedup vs baseline: 2.2315x; 1.2548x over previous
#include <cuda_runtime.h>
#include <cuda_fp16.h>
#include <mma.h>

using namespace nvcuda;

#define IN   128
#define HID  128
#define OUTF 64
#define NMAX 50000
#define EMAX 1600000

// Scratch (device globals; no allocation allowed)
__device__ __align__(128) unsigned int g_y1h[NMAX * HID / 2];   // x@W1 (un-scaled), half2 packed
__device__ __align__(128) unsigned int g_hh [NMAX * HID / 2];   // relu hidden, half2 packed
__device__ __align__(128) unsigned int g_y2h[NMAX * OUTF / 2];  // (h@W2)*dinv[row], half2 packed
__device__ __align__(128) float g_z [NMAX * OUTF];              // final embeddings
__device__ __align__(16) __half g_W1h[IN * HID];
__device__ __align__(16) __half g_W2h[HID * OUTF];
__device__ float g_dinv[NMAX];
__device__ int   g_cnt[NMAX];
__device__ int   g_cur[NMAX];
__device__ int   g_off[NMAX + 1];
__device__ int   g_bsum[256];
__device__ int   g_csr_src[EMAX];

// ---------------- weight conversion (fp32 -> fp16) ----------------
__global__ void k_convW(const float* __restrict__ W1, const float* __restrict__ W2) {
    int i = blockIdx.x * blockDim.x + threadIdx.x;
    if (i < IN * HID) g_W1h[i] = __float2half(W1[i]);
    else if (i < IN * HID + HID * OUTF) g_W2h[i - IN * HID] = __float2half(W2[i - IN * HID]);
}

// ---------------- CSR build ----------------
__global__ void k_zero_cnt(int n) {
    int i = blockIdx.x * blockDim.x + threadIdx.x;
    if (i < n) g_cnt[i] = 0;
}

__global__ void __launch_bounds__(256) k_count(const int* __restrict__ ei, int E) {
    int stride = gridDim.x * blockDim.x;
    int e = blockIdx.x * blockDim.x + threadIdx.x;
#pragma unroll 4
    for (int k = 0; k < 4; k++) {
        int idx = e + k * stride;
        if (idx < E) atomicAdd(&g_cnt[ei[E + idx]], 1);  // dst
    }
}

// Phase A: per-block (256 elems) exclusive scan; block sums to g_bsum
__global__ void __launch_bounds__(256) k_scanA(int n) {
    __shared__ int wsum[8];
    int i = blockIdx.x * 256 + threadIdx.x;
    int lane = threadIdx.x & 31, warp = threadIdx.x >> 5;
    int v = (i < n) ? g_cnt[i] : 0;
    int x = v;
#pragma unroll
    for (int o = 1; o < 32; o <<= 1) {
        int t = __shfl_up_sync(0xffffffffu, x, o);
        if (lane >= o) x += t;
    }
    if (lane == 31) wsum[warp] = x;
    __syncthreads();
    if (threadIdx.x < 8) {
        int y = wsum[threadIdx.x];
#pragma unroll
        for (int o = 1; o < 8; o <<= 1) {
            int t = __shfl_up_sync(0xffu, y, o);
            if ((int)threadIdx.x >= o) y += t;
        }
        wsum[threadIdx.x] = y;
    }
    __syncthreads();
    int incl = x + (warp ? wsum[warp - 1] : 0);
    if (i < n) g_off[i] = incl - v;          // exclusive within block
    if (threadIdx.x == 0) g_bsum[blockIdx.x] = wsum[7];
}

// Phase B: scan of block sums (nb <= 256), also writes total to g_off[n]
__global__ void __launch_bounds__(256) k_scanB(int nb, int n) {
    __shared__ int wsum[8];
    int t = threadIdx.x;
    int lane = t & 31, warp = t >> 5;
    int v = (t < nb) ? g_bsum[t] : 0;
    int x = v;
#pragma unroll
    for (int o = 1; o < 32; o <<= 1) {
        int tt = __shfl_up_sync(0xffffffffu, x, o);
        if (lane >= o) x += tt;
    }
    if (lane == 31) wsum[warp] = x;
    __syncthreads();
    if (t < 8) {
        int y = wsum[t];
#pragma unroll
        for (int o = 1; o < 8; o <<= 1) {
            int tt = __shfl_up_sync(0xffu, y, o);
            if (t >= o) y += tt;
        }
        wsum[t] = y;
    }
    __syncthreads();
    int incl = x + (warp ? wsum[warp - 1] : 0);
    if (t < nb) g_bsum[t] = incl - v;        // exclusive block offsets
    if (t == 0) g_off[n] = wsum[7];          // total edges
}

// Phase C: finalize offsets, dinv, cursors
__global__ void __launch_bounds__(256) k_scanC(int n) {
    int i = blockIdx.x * 256 + threadIdx.x;
    if (i < n) {
        g_off[i] += g_bsum[blockIdx.x];
        g_dinv[i] = rsqrtf((float)(g_cnt[i] + 1));  // +1 self loop
        g_cur[i] = 0;
    }
}

__global__ void __launch_bounds__(256) k_fill(const int* __restrict__ ei, int E) {
    int stride = gridDim.x * blockDim.x;
    int e = blockIdx.x * blockDim.x + threadIdx.x;
#pragma unroll 4
    for (int k = 0; k < 4; k++) {
        int idx = e + k * stride;
        if (idx < E) {
            int s = ei[idx];
            int d = ei[E + idx];
            int pos = g_off[d] + atomicAdd(&g_cur[d], 1);
            g_csr_src[pos] = s;
        }
    }
}

// ---------------- GEMM1 (wmma): y1 = x @ W1, fp16 out, NO dinv ----------------
// Block 256 = 8 warps, 64-row tile. warp = 16 rows x 64 cols.
__global__ void __launch_bounds__(256) k_gemm1(const float* __restrict__ x, int n) {
    __shared__ __align__(16) unsigned char sm[49152];  // xs 16KB | ws 32KB ; fbuf reuses
    __half* xs = (__half*)sm;                 // [64][128]
    __half* ws = (__half*)(sm + 16384);       // [128][128]
    int row0 = blockIdx.x * 64;
    int tid = threadIdx.x;

    // load x tile -> fp16
    for (int i = tid; i < 64 * 32; i += 256) {
        int r = i >> 5, c4 = i & 31;
        float4 v = make_float4(0.f, 0.f, 0.f, 0.f);
        if (row0 + r < n) v = ((const float4*)x)[(size_t)(row0 + r) * 32 + c4];
        half2 h0 = __float22half2_rn(make_float2(v.x, v.y));
        half2 h1 = __float22half2_rn(make_float2(v.z, v.w));
        uint2 p; p.x = *(unsigned int*)&h0; p.y = *(unsigned int*)&h1;
        ((uint2*)xs)[i] = p;
    }
    // load W1h (16384 half = 4096 uint4/... use uint4: 2048 loads)
    for (int i = tid; i < 2048; i += 256)
        ((uint4*)ws)[i] = ((const uint4*)g_W1h)[i];
    __syncthreads();

    int warp = tid >> 5;
    int rowg = warp >> 1;         // 0..3 -> 16-row group
    int colh = warp & 1;          // 0..1 -> 64-col half

    wmma::fragment<wmma::accumulator, 16, 16, 16, float> c[4];
#pragma unroll
    for (int t = 0; t < 4; t++) wmma::fill_fragment(c[t], 0.f);

#pragma unroll
    for (int k = 0; k < 8; k++) {
        wmma::fragment<wmma::matrix_a, 16, 16, 16, __half, wmma::row_major> a;
        wmma::load_matrix_sync(a, xs + (rowg * 16) * 128 + k * 16, 128);
#pragma unroll
        for (int t = 0; t < 4; t++) {
            wmma::fragment<wmma::matrix_b, 16, 16, 16, __half, wmma::row_major> b;
            wmma::load_matrix_sync(b, ws + (k * 16) * 128 + colh * 64 + t * 16, 128);
            wmma::mma_sync(c[t], a, b, c[t]);
        }
    }
    __syncthreads();
    float* fbuf = (float*)sm;  // [64][128]
#pragma unroll
    for (int t = 0; t < 4; t++)
        wmma::store_matrix_sync(fbuf + (rowg * 16) * 128 + colh * 64 + t * 16, c[t], 128, wmma::mem_row_major);
    __syncthreads();

    for (int i = tid; i < 64 * 32; i += 256) {
        int r = i >> 5, c4 = i & 31;
        int row = row0 + r;
        if (row < n) {
            float4 v = ((float4*)fbuf)[i];
            half2 h0 = __float22half2_rn(make_float2(v.x, v.y));
            half2 h1 = __float22half2_rn(make_float2(v.z, v.w));
            uint2 p; p.x = *(unsigned int*)&h0; p.y = *(unsigned int*)&h1;
            ((uint2*)g_y1h)[(size_t)row * 32 + c4] = p;
        }
    }
}

// ---------------- agg1: h = relu((sum_{s in N+self} y1[s]*dinv[s]) * dinv[i] + b1), fp16 out ----
__global__ void __launch_bounds__(256) k_agg1(const float* __restrict__ b1, int n) {
    int node = (int)((blockIdx.x * 256u + threadIdx.x) >> 5);
    int lane = threadIdx.x & 31;
    if (node >= n) return;
    int beg = g_off[node];
    int end = g_off[node + 1];
    float dself = g_dinv[node];

    const uint2* y = (const uint2*)g_y1h;
    uint2 ps = y[(size_t)node * 32 + lane];  // self
    float2 a0 = __half22float2(*(half2*)&ps.x);
    float2 a1 = __half22float2(*(half2*)&ps.y);
    float4 acc = make_float4(a0.x * dself, a0.y * dself, a1.x * dself, a1.y * dself);

    int j = beg;
    for (; j + 3 < end; j += 4) {
        int s0 = __ldg(&g_csr_src[j]);
        int s1 = __ldg(&g_csr_src[j + 1]);
        int s2 = __ldg(&g_csr_src[j + 2]);
        int s3 = __ldg(&g_csr_src[j + 3]);
        float d0 = __ldg(&g_dinv[s0]);
        float d1 = __ldg(&g_dinv[s1]);
        float d2 = __ldg(&g_dinv[s2]);
        float d3 = __ldg(&g_dinv[s3]);
        uint2 p0 = y[(size_t)s0 * 32 + lane];
        uint2 p1 = y[(size_t)s1 * 32 + lane];
        uint2 p2 = y[(size_t)s2 * 32 + lane];
        uint2 p3 = y[(size_t)s3 * 32 + lane];
        float2 u, v;
        u = __half22float2(*(half2*)&p0.x); v = __half22float2(*(half2*)&p0.y);
        acc.x += u.x * d0; acc.y += u.y * d0; acc.z += v.x * d0; acc.w += v.y * d0;
        u = __half22float2(*(half2*)&p1.x); v = __half22float2(*(half2*)&p1.y);
        acc.x += u.x * d1; acc.y += u.y * d1; acc.z += v.x * d1; acc.w += v.y * d1;
        u = __half22float2(*(half2*)&p2.x); v = __half22float2(*(half2*)&p2.y);
        acc.x += u.x * d2; acc.y += u.y * d2; acc.z += v.x * d2; acc.w += v.y * d2;
        u = __half22float2(*(half2*)&p3.x); v = __half22float2(*(half2*)&p3.y);
        acc.x += u.x * d3; acc.y += u.y * d3; acc.z += v.x * d3; acc.w += v.y * d3;
    }
    for (; j < end; j++) {
        int s0 = __ldg(&g_csr_src[j]);
        float d0 = __ldg(&g_dinv[s0]);
        uint2 p0 = y[(size_t)s0 * 32 + lane];
        float2 u = __half22float2(*(half2*)&p0.x);
        float2 v = __half22float2(*(half2*)&p0.y);
        acc.x += u.x * d0; acc.y += u.y * d0; acc.z += v.x * d0; acc.w += v.y * d0;
    }

    float4 bb = ((const float4*)b1)[lane];
    float2 h0, h1;
    h0.x = fmaxf(acc.x * dself + bb.x, 0.f);
    h0.y = fmaxf(acc.y * dself + bb.y, 0.f);
    h1.x = fmaxf(acc.z * dself + bb.z, 0.f);
    h1.y = fmaxf(acc.w * dself + bb.w, 0.f);
    half2 q0 = __float22half2_rn(h0);
    half2 q1 = __float22half2_rn(h1);
    uint2 p; p.x = *(unsigned int*)&q0; p.y = *(unsigned int*)&q1;
    ((uint2*)g_hh)[(size_t)node * 32 + lane] = p;
}

// ---------------- GEMM2 (wmma): y2 = (h @ W2) * dinv[row], fp16 out ----------------
__global__ void __launch_bounds__(256) k_gemm2(int n) {
    __shared__ __align__(16) unsigned char sm[32768];  // hs 16KB | w2s 16KB ; fbuf reuses
    __half* hs  = (__half*)sm;             // [64][128]
    __half* w2s = (__half*)(sm + 16384);   // [128][64]
    int row0 = blockIdx.x * 64;
    int tid = threadIdx.x;

    for (int i = tid; i < 64 * 32; i += 256) {
        int r = i >> 5;
        uint2 p = make_uint2(0u, 0u);
        if (row0 + r < n) p = ((const uint2*)g_hh)[(size_t)(row0 + r) * 32 + (i & 31)];
        ((uint2*)hs)[i] = p;
    }
    for (int i = tid; i < 1024; i += 256)  // 8192 half = 1024 uint4
        ((uint4*)w2s)[i] = ((const uint4*)g_W2h)[i];
    __syncthreads();

    int warp = tid >> 5;
    int rowg = warp >> 1;
    int colh = warp & 1;  // 32-col half

    wmma::fragment<wmma::accumulator, 16, 16, 16, float> c[2];
#pragma unroll
    for (int t = 0; t < 2; t++) wmma::fill_fragment(c[t], 0.f);

#pragma unroll
    for (int k = 0; k < 8; k++) {
        wmma::fragment<wmma::matrix_a, 16, 16, 16, __half, wmma::row_major> a;
        wmma::load_matrix_sync(a, hs + (rowg * 16) * 128 + k * 16, 128);
#pragma unroll
        for (int t = 0; t < 2; t++) {
            wmma::fragment<wmma::matrix_b, 16, 16, 16, __half, wmma::row_major> b;
            wmma::load_matrix_sync(b, w2s + (k * 16) * 64 + colh * 32 + t * 16, 64);
            wmma::mma_sync(c[t], a, b, c[t]);
        }
    }
    __syncthreads();
    float* fbuf = (float*)sm;  // [64][64]
#pragma unroll
    for (int t = 0; t < 2; t++)
        wmma::store_matrix_sync(fbuf + (rowg * 16) * 64 + colh * 32 + t * 16, c[t], 64, wmma::mem_row_major);
    __syncthreads();

    for (int i = tid; i < 64 * 16; i += 256) {
        int r = i >> 4, c4 = i & 15;
        int row = row0 + r;
        if (row < n) {
            float d = g_dinv[row];
            float4 v = ((float4*)fbuf)[i];
            half2 h0 = __float22half2_rn(make_float2(v.x * d, v.y * d));
            half2 h1 = __float22half2_rn(make_float2(v.z * d, v.w * d));
            uint2 p; p.x = *(unsigned int*)&h0; p.y = *(unsigned int*)&h1;
            ((uint2*)g_y2h)[(size_t)row * 16 + c4] = p;
        }
    }
}

// ---------------- agg2: z = (y2[i] + sum y2[src]) * dinv[i] + b2 ----------------
__global__ void __launch_bounds__(256) k_agg2(const float* __restrict__ b2, int n) {
    int node = (int)((blockIdx.x * 256u + threadIdx.x) >> 5);
    int lane = threadIdx.x & 31;
    if (node >= n) return;
    int beg = g_off[node];
    int end = g_off[node + 1];

    const unsigned int* y = g_y2h;
    unsigned int ps = y[(size_t)node * 32 + lane];  // self (already * dinv[self])
    float2 acc = __half22float2(*(half2*)&ps);

    int j = beg;
    for (; j + 3 < end; j += 4) {
        int s0 = __ldg(&g_csr_src[j]);
        int s1 = __ldg(&g_csr_src[j + 1]);
        int s2 = __ldg(&g_csr_src[j + 2]);
        int s3 = __ldg(&g_csr_src[j + 3]);
        unsigned int p0 = y[(size_t)s0 * 32 + lane];
        unsigned int p1 = y[(size_t)s1 * 32 + lane];
        unsigned int p2 = y[(size_t)s2 * 32 + lane];
        unsigned int p3 = y[(size_t)s3 * 32 + lane];
        float2 u;
        u = __half22float2(*(half2*)&p0); acc.x += u.x; acc.y += u.y;
        u = __half22float2(*(half2*)&p1); acc.x += u.x; acc.y += u.y;
        u = __half22float2(*(half2*)&p2); acc.x += u.x; acc.y += u.y;
        u = __half22float2(*(half2*)&p3); acc.x += u.x; acc.y += u.y;
    }
    for (; j < end; j++) {
        int s0 = __ldg(&g_csr_src[j]);
        unsigned int p0 = y[(size_t)s0 * 32 + lane];
        float2 u = __half22float2(*(half2*)&p0);
        acc.x += u.x; acc.y += u.y;
    }

    float d = g_dinv[node];
    float2 bb = ((const float2*)b2)[lane];
    float2 z = make_float2(acc.x * d + bb.x, acc.y * d + bb.y);
    ((float2*)g_z)[(size_t)node * 32 + lane] = z;
}

// ---------------- decode ----------------
__global__ void __launch_bounds__(256) k_decode(const int* __restrict__ eli, int EL,
                                                float* __restrict__ out) {
    int w = (int)((blockIdx.x * 256u + threadIdx.x) >> 5);
    int lane = threadIdx.x & 31;
    if (w >= EL) return;
    int a = eli[w];
    int b = eli[EL + w];
    float2 za = ((const float2*)g_z)[(size_t)a * 32 + lane];
    float2 zb = ((const float2*)g_z)[(size_t)b * 32 + lane];
    float s = za.x * zb.x + za.y * zb.y;
#pragma unroll
    for (int o = 16; o; o >>= 1) s += __shfl_xor_sync(0xffffffffu, s, o);
    if (lane == 0) out[w] = s;
}

// ---------------- side stream for fork-join capture ----------------
static cudaStream_t g_s1;
static cudaEvent_t g_ev0, g_ev1;
namespace {
struct GInit {
    GInit() {
        cudaStreamCreateWithFlags(&g_s1, cudaStreamNonBlocking);
        cudaEventCreateWithFlags(&g_ev0, cudaEventDisableTiming);
        cudaEventCreateWithFlags(&g_ev1, cudaEventDisableTiming);
    }
};
GInit g_init;
}

extern "C" void kernel_launch(void* const* d_in, const int* in_sizes, int n_in,
                              void* d_out, int out_size) {
    const float* x   = (const float*)d_in[0];
    const int*   ei  = (const int*)d_in[1];
    const int*   eli = (const int*)d_in[2];
    const float* W1  = (const float*)d_in[3];
    const float* b1  = (const float*)d_in[4];
    const float* W2  = (const float*)d_in[5];
    const float* b2  = (const float*)d_in[6];
    float* out = (float*)d_out;

    int N  = in_sizes[0] / IN;
    int E  = in_sizes[1] / 2;
    int EL = in_sizes[2] / 2;
    int quarter = (E + 3) / 4;
    int nb = (N + 255) / 256;

    // fork: branch B (weights conv + gemm1) on side stream
    cudaEventRecord(g_ev0, 0);
    cudaStreamWaitEvent(g_s1, g_ev0, 0);
    k_convW<<<(IN * HID + HID * OUTF + 255) / 256, 256, 0, g_s1>>>(W1, W2);
    k_gemm1<<<(N + 63) / 64, 256, 0, g_s1>>>(x, N);
    cudaEventRecord(g_ev1, g_s1);

    // branch A: CSR build (by dst) on main stream
    k_zero_cnt<<<nb, 256>>>(N);
    k_count<<<(quarter + 255) / 256, 256>>>(ei, E);
    k_scanA<<<nb, 256>>>(N);
    k_scanB<<<1, 256>>>(nb, N);
    k_scanC<<<nb, 256>>>(N);
    k_fill<<<(quarter + 255) / 256, 256>>>(ei, E);

    // join
    cudaStreamWaitEvent(0, g_ev1, 0);

    // layer 1 aggregate, layer 2, decode
    k_agg1<<<(N * 32 + 255) / 256, 256>>>(b1, N);
    k_gemm2<<<(N + 63) / 64, 256>>>(N);
    k_agg2<<<(N * 32 + 255) / 256, 256>>>(b2, N);
    k_decode<<<(EL * 32 + 255) / 256, 256>>>(eli, EL, out);
}